// round 11
// baseline (speedup 1.0000x reference)
#include <cuda_runtime.h>
#include <math.h>

#define NN 8192
#define FF 8
#define THRESH 0.9f
#define ATPB 128
#define FTPB 256
#define TILE 128
#define NT (NN / TILE)
#define NFIDB (NT * (NT + 1) / 2)

typedef unsigned long long ull;

__device__ float g_corr[NN * FF];
__device__ float g_sums[NN * FF];
__device__ float g_xn[NN * FF];     // normalized features, row-major
__device__ float g_wt[792];         // packed MLP weights

// ---------- packed f32x2 helpers ----------
__device__ __forceinline__ ull pk2(float x, float y) {
    ull r; asm("mov.b64 %0, {%1, %2};" : "=l"(r) : "f"(x), "f"(y)); return r;
}
__device__ __forceinline__ void up2(float& x, float& y, ull v) {
    asm("mov.b64 {%0, %1}, %2;" : "=f"(x), "=f"(y) : "l"(v));
}
__device__ __forceinline__ void fma2(ull& d, ull a, ull b) {
    asm("fma.rn.f32x2 %0, %1, %2, %0;" : "+l"(d) : "l"(a), "l"(b));
}
__device__ __forceinline__ float tanh_a(float v) {
    float r; asm("tanh.approx.f32 %0, %1;" : "=f"(r) : "f"(v)); return r;
}

// packed weight offsets
#define OW0 0
#define OB0 128
#define OW1 144
#define OB1 400
#define OW2 416
#define OB2 608
#define OW3 620
#define OB3 716
#define OW4 724
#define OB4 756
#define OW5 760
#define OB5 776
#define OW6 780
#define OB6 784

// ---------- kernel: pack MLP weights contiguously ----------
__global__ void __launch_bounds__(128) k_packw(
    const float* __restrict__ Wfm, const float* __restrict__ bfm,
    const float* __restrict__ Wc1, const float* __restrict__ bc1,
    const float* __restrict__ Wp1, const float* __restrict__ bp1,
    const float* __restrict__ Wc2, const float* __restrict__ bc2,
    const float* __restrict__ Wp2, const float* __restrict__ bp2,
    const float* __restrict__ Wc3, const float* __restrict__ bc3,
    const float* __restrict__ Wh,  const float* __restrict__ bh)
{
    int t = threadIdx.x;
    g_wt[OW0 + t] = Wfm[t];
    if (t < 16)  g_wt[OB0 + t] = bfm[t];
    g_wt[OW1 + t]       = Wc1[t];
    g_wt[OW1 + 128 + t] = Wc1[128 + t];
    if (t < 16)  g_wt[OB1 + t] = bc1[t];
    g_wt[OW2 + t] = Wp1[t];
    if (t < 64)  g_wt[OW2 + 128 + t] = Wp1[128 + t];
    if (t < 12)  g_wt[OB2 + t] = bp1[t];
    if (t < 96)  g_wt[OW3 + t] = Wc2[t];
    if (t < 8)   g_wt[OB3 + t] = bc2[t];
    if (t < 32)  g_wt[OW4 + t] = Wp2[t];
    if (t < 4)   g_wt[OB4 + t] = bp2[t];
    if (t < 16)  g_wt[OW5 + t] = Wc3[t];
    if (t < 4)   g_wt[OB5 + t] = bc3[t];
    if (t < 4)   g_wt[OW6 + t] = Wh[t];
    if (t == 0)  g_wt[OB6] = bh[0];
}

// ---------- kernel: normalize features ----------
__global__ void __launch_bounds__(128) k_prep(const float* __restrict__ x) {
    int i = blockIdx.x * 128 + threadIdx.x;
    float4 a = *(const float4*)(x + i * FF);
    float4 b = *(const float4*)(x + i * FF + 4);
    float s = a.x*a.x + a.y*a.y + a.z*a.z + a.w*a.w
            + b.x*b.x + b.y*b.y + b.z*b.z + b.w*b.w;
    float inv = 1.0f / (sqrtf(s) + 1e-12f);
    a.x *= inv; a.y *= inv; a.z *= inv; a.w *= inv;
    b.x *= inv; b.y *= inv; b.z *= inv; b.w *= inv;
    *(float4*)(g_xn + i * FF)     = a;
    *(float4*)(g_xn + i * FF + 4) = b;
}

// ---------- kernel: fidelity hits over upper-triangle 128x128 tiles ----------
__global__ void __launch_bounds__(FTPB) k_fid(const float* __restrict__ adj,
                                              const float* __restrict__ x) {
    __shared__ ull  sIp[TILE * FF];
    __shared__ float sJ[FF][TILE];

    int b = blockIdx.x;
    int ti = (int)(((2 * NT + 1) - sqrtf((float)((2 * NT + 1) * (2 * NT + 1)) - 8.0f * (float)b)) * 0.5f);
    if (ti < 0) ti = 0;
    if (ti > NT - 1) ti = NT - 1;
#define RS(r) ((r) * NT - ((r) * ((r) - 1)) / 2)
    while (ti > 0 && RS(ti) > b) --ti;
    while (RS(ti + 1) <= b) ++ti;
    int tj = ti + (b - RS(ti));
#undef RS

    int t = threadIdx.x;
    {
        int r = t & 127;
        int row = ((t < 128) ? ti : tj) * TILE + r;
        float4 a = *(const float4*)(g_xn + row * FF);
        float4 c = *(const float4*)(g_xn + row * FF + 4);
        float v[8] = {a.x, a.y, a.z, a.w, c.x, c.y, c.z, c.w};
        if (t < 128) {
#pragma unroll
            for (int f = 0; f < FF; ++f) sIp[r * FF + f] = pk2(v[f], v[f]);
        } else {
#pragma unroll
            for (int f = 0; f < FF; ++f) sJ[f][r] = v[f];
        }
    }
    __syncthreads();

    int w = t >> 5, lane = t & 31;
    int j0 = lane * 4;
    ull xj0[FF], xj1[FF];
#pragma unroll
    for (int f = 0; f < FF; ++f) {
        float4 v = *(const float4*)&sJ[f][j0];
        xj0[f] = pk2(v.x, v.y);
        xj1[f] = pk2(v.z, v.w);
    }
    int gjb = tj * TILE + j0;

#pragma unroll 8
    for (int ii = 0; ii < 16; ++ii) {
        int i = w * 16 + ii;
        ull d0 = 0ULL, d1 = 0ULL;
#pragma unroll
        for (int f = 0; f < FF; ++f) {
            ull xi = sIp[i * FF + f];
            fma2(d0, xi, xj0[f]);
            fma2(d1, xi, xj1[f]);
        }
        float da, db, dc, dd;
        up2(da, db, d0); up2(dc, dd, d1);
        int gi = ti * TILE + i;
        bool h0 = (da * da >= THRESH) && (gi < gjb + 0);
        bool h1 = (db * db >= THRESH) && (gi < gjb + 1);
        bool h2 = (dc * dc >= THRESH) && (gi < gjb + 2);
        bool h3 = (dd * dd >= THRESH) && (gi < gjb + 3);
        if (h0 | h1 | h2 | h3) {
            float4 xia = *(const float4*)(x + gi * FF);
            float4 xib = *(const float4*)(x + gi * FF + 4);
            float xi8[8] = {xia.x, xia.y, xia.z, xia.w, xib.x, xib.y, xib.z, xib.w};
            bool hh[4] = {h0, h1, h2, h3};
#pragma unroll
            for (int k = 0; k < 4; ++k) {
                if (hh[k]) {
                    int gj = gjb + k;
                    float aij = __ldg(adj + (size_t)gi * NN + gj);
                    float aji = __ldg(adj + (size_t)gj * NN + gi);
                    float wi = 1.0f - aij, wj = 1.0f - aji;
#pragma unroll
                    for (int f = 0; f < FF; ++f) {
                        atomicAdd(&g_corr[gi * FF + f], wi * __ldg(x + gj * FF + f));
                        atomicAdd(&g_corr[gj * FF + f], wj * xi8[f]);
                    }
                }
            }
        }
    }
}

// ---------- kernel: stream adjacency, NO smem, x direct from L1 ----------
// x row-major (j,f): a 16B load at x[j*8] IS the packed feature-pair operand.
__global__ void __launch_bounds__(ATPB, 4) k_adj(const float* __restrict__ adj,
                                                 const float* __restrict__ x) {
    int tid = threadIdx.x, warp = tid >> 5, lane = tid & 31;
    int rowbase = blockIdx.x * 16 + warp * 4;
    const float* ap = adj + (size_t)rowbase * NN + lane * 4;
    const ulonglong2* xq = (const ulonglong2*)x;   // 2 per j-row

    ull acc[16];   // [r*4+p] : packed (f=2p, f=2p+1) sums
#pragma unroll
    for (int k = 0; k < 16; ++k) acc[k] = 0ULL;

    float4 Abuf[4], Bbuf[4];

#define LOAD4(BUF, OFF) do {                                                    \
    _Pragma("unroll")                                                           \
    for (int r = 0; r < 4; ++r)                                                 \
        BUF[r] = __ldcs((const float4*)(ap + (size_t)r * NN + (OFF)));          \
    } while (0)

#define GETC(V, J) ((J) == 0 ? (V).x : (J) == 1 ? (V).y : (J) == 2 ? (V).z : (V).w)

#define COMPX(BUF, JBASE) do {                                                  \
    int jl = (JBASE) + lane * 4;                                                \
    ulonglong2 Xa0 = __ldg(xq + (size_t)jl * 2 + 0);                            \
    ulonglong2 Xb0 = __ldg(xq + (size_t)jl * 2 + 1);                            \
    ulonglong2 Xa1 = __ldg(xq + (size_t)jl * 2 + 2);                            \
    ulonglong2 Xb1 = __ldg(xq + (size_t)jl * 2 + 3);                            \
    ulonglong2 Xa2 = __ldg(xq + (size_t)jl * 2 + 4);                            \
    ulonglong2 Xb2 = __ldg(xq + (size_t)jl * 2 + 5);                            \
    ulonglong2 Xa3 = __ldg(xq + (size_t)jl * 2 + 6);                            \
    ulonglong2 Xb3 = __ldg(xq + (size_t)jl * 2 + 7);                            \
    _Pragma("unroll")                                                           \
    for (int r = 0; r < 4; ++r) {                                               \
        float a0 = GETC(BUF[r], 0); ull d0 = pk2(a0, a0);                       \
        fma2(acc[r * 4 + 0], d0, Xa0.x); fma2(acc[r * 4 + 1], d0, Xa0.y);       \
        fma2(acc[r * 4 + 2], d0, Xb0.x); fma2(acc[r * 4 + 3], d0, Xb0.y);       \
        float a1 = GETC(BUF[r], 1); ull d1 = pk2(a1, a1);                       \
        fma2(acc[r * 4 + 0], d1, Xa1.x); fma2(acc[r * 4 + 1], d1, Xa1.y);       \
        fma2(acc[r * 4 + 2], d1, Xb1.x); fma2(acc[r * 4 + 3], d1, Xb1.y);       \
        float a2 = GETC(BUF[r], 2); ull d2 = pk2(a2, a2);                       \
        fma2(acc[r * 4 + 0], d2, Xa2.x); fma2(acc[r * 4 + 1], d2, Xa2.y);       \
        fma2(acc[r * 4 + 2], d2, Xb2.x); fma2(acc[r * 4 + 3], d2, Xb2.y);       \
        float a3 = GETC(BUF[r], 3); ull d3 = pk2(a3, a3);                       \
        fma2(acc[r * 4 + 0], d3, Xa3.x); fma2(acc[r * 4 + 1], d3, Xa3.y);       \
        fma2(acc[r * 4 + 2], d3, Xb3.x); fma2(acc[r * 4 + 3], d3, Xb3.y);       \
    } } while (0)

    LOAD4(Abuf, 0);   // prime adjacency pipeline

#pragma unroll 1
    for (int j = 0; j < NN; j += 256) {
        LOAD4(Bbuf, j + 128);          // prefetch phase B while computing A
        COMPX(Abuf, j);
        if (j + 256 < NN) LOAD4(Abuf, j + 256);
        COMPX(Bbuf, j + 128);
    }

    // unpack packed feature-pair sums, butterfly-reduce across the 32 j-lanes
    float v[32];
#pragma unroll
    for (int r = 0; r < 4; ++r)
#pragma unroll
        for (int p = 0; p < 4; ++p)
            up2(v[r * 8 + 2 * p], v[r * 8 + 2 * p + 1], acc[r * 4 + p]);
#pragma unroll
    for (int o = 16; o; o >>= 1)
#pragma unroll
        for (int k = 0; k < 32; ++k) v[k] += __shfl_xor_sync(0xffffffffu, v[k], o);

    g_sums[(rowbase + (lane >> 3)) * FF + (lane & 7)] = v[lane];
}

// ---------- kernel: per-row MLP tail ----------
__global__ void __launch_bounds__(128) k_post(float* __restrict__ out) {
    __shared__ float swt[792];
    int tid = threadIdx.x;
#pragma unroll
    for (int k = 0; k < 7; ++k) {
        int idx = tid + k * 128;
        if (idx < 792) swt[idx] = g_wt[idx];
    }
    __syncthreads();

    int row = blockIdx.x * 128 + tid;
    float s[8];
#pragma unroll
    for (int f = 0; f < FF; ++f) s[f] = g_sums[row * FF + f] + g_corr[row * FF + f];

    float h0[16];
#pragma unroll
    for (int o = 0; o < 16; ++o) {
        float t = swt[OB0 + o];
#pragma unroll
        for (int i = 0; i < 8; ++i) t = fmaf(s[i], swt[OW0 + i * 16 + o], t);
        h0[o] = tanh_a(t);
    }
    float h1[16];
#pragma unroll
    for (int o = 0; o < 16; ++o) {
        float t = swt[OB1 + o];
#pragma unroll
        for (int i = 0; i < 16; ++i) t = fmaf(h0[i], swt[OW1 + i * 16 + o], t);
        h1[o] = tanh_a(t);
    }
    float h2[12];
#pragma unroll
    for (int o = 0; o < 12; ++o) {
        float t = swt[OB2 + o];
#pragma unroll
        for (int i = 0; i < 16; ++i) t = fmaf(h1[i], swt[OW2 + i * 12 + o], t);
        h2[o] = tanh_a(t);
    }
    float h3[8];
#pragma unroll
    for (int o = 0; o < 8; ++o) {
        float t = swt[OB3 + o];
#pragma unroll
        for (int i = 0; i < 12; ++i) t = fmaf(h2[i], swt[OW3 + i * 8 + o], t);
        h3[o] = tanh_a(t);
    }
    float h4[4];
#pragma unroll
    for (int o = 0; o < 4; ++o) {
        float t = swt[OB4 + o];
#pragma unroll
        for (int i = 0; i < 8; ++i) t = fmaf(h3[i], swt[OW4 + i * 4 + o], t);
        h4[o] = tanh_a(t);
    }
    float h5[4];
#pragma unroll
    for (int o = 0; o < 4; ++o) {
        float t = swt[OB5 + o];
#pragma unroll
        for (int i = 0; i < 4; ++i) t = fmaf(h4[i], swt[OW5 + i * 4 + o], t);
        h5[o] = tanh_a(t);
    }
    float z = swt[OB6];
#pragma unroll
    for (int i = 0; i < 4; ++i) z = fmaf(h5[i], swt[OW6 + i], z);
    out[row] = 1.0f / (1.0f + expf(-z));
}

extern "C" void kernel_launch(void* const* d_in, const int* in_sizes, int n_in,
                              void* d_out, int out_size) {
    const float* adj = (const float*)d_in[0];
    const float* x   = (const float*)d_in[1];
    const float* Wfm = (const float*)d_in[2];
    const float* bfm = (const float*)d_in[3];
    const float* Wc1 = (const float*)d_in[4];
    const float* bc1 = (const float*)d_in[5];
    const float* Wp1 = (const float*)d_in[6];
    const float* bp1 = (const float*)d_in[7];
    const float* Wc2 = (const float*)d_in[8];
    const float* bc2 = (const float*)d_in[9];
    const float* Wp2 = (const float*)d_in[10];
    const float* bp2 = (const float*)d_in[11];
    const float* Wc3 = (const float*)d_in[12];
    const float* bc3 = (const float*)d_in[13];
    const float* Wh  = (const float*)d_in[14];
    const float* bh  = (const float*)d_in[15];
    float* out = (float*)d_out;

    static cudaStream_t s2 = nullptr;
    static cudaEvent_t e0 = nullptr, e1 = nullptr;
    if (s2 == nullptr) {
        cudaStreamCreateWithFlags(&s2, cudaStreamNonBlocking);
        cudaEventCreateWithFlags(&e0, cudaEventDisableTiming);
        cudaEventCreateWithFlags(&e1, cudaEventDisableTiming);
    }

    void* corr_ptr = nullptr;
    cudaGetSymbolAddress(&corr_ptr, g_corr);

    // k_adj issued first (fully resident); fid branch time-shares idle slots.
    cudaEventRecord(e0, 0);
    k_adj<<<NN / 16, ATPB>>>(adj, x);

    cudaStreamWaitEvent(s2, e0, 0);
    cudaMemsetAsync(corr_ptr, 0, NN * FF * sizeof(float), s2);
    k_packw<<<1, 128, 0, s2>>>(Wfm, bfm, Wc1, bc1, Wp1, bp1, Wc2, bc2,
                               Wp2, bp2, Wc3, bc3, Wh, bh);
    k_prep<<<NN / 128, 128, 0, s2>>>(x);
    k_fid<<<NFIDB, FTPB, 0, s2>>>(adj, x);
    cudaEventRecord(e1, s2);

    cudaStreamWaitEvent(0, e1, 0);
    k_post<<<NN / 128, 128>>>(out);
}

// round 12
// speedup vs baseline: 1.9232x; 1.9232x over previous
#include <cuda_runtime.h>
#include <math.h>

#define NN 8192
#define FF 8
#define THRESH 0.9f
#define CH 1024
#define ATPB 128
#define FTPB 256
#define TILE 128
#define NT (NN / TILE)
#define NFIDB (NT * (NT + 1) / 2)

typedef unsigned long long ull;

__device__ float g_corr[NN * FF];
__device__ float g_sums[NN * FF];
__device__ float g_xn[NN * FF];     // normalized features, row-major
__device__ float g_wt[792];         // packed MLP weights

// ---------- packed f32x2 helpers ----------
__device__ __forceinline__ ull pk2(float x, float y) {
    ull r; asm("mov.b64 %0, {%1, %2};" : "=l"(r) : "f"(x), "f"(y)); return r;
}
__device__ __forceinline__ void up2(float& x, float& y, ull v) {
    asm("mov.b64 {%0, %1}, %2;" : "=f"(x), "=f"(y) : "l"(v));
}
__device__ __forceinline__ void fma2(ull& d, ull a, ull b) {
    asm("fma.rn.f32x2 %0, %1, %2, %0;" : "+l"(d) : "l"(a), "l"(b));
}
__device__ __forceinline__ float tanh_a(float v) {
    float r; asm("tanh.approx.f32 %0, %1;" : "=f"(r) : "f"(v)); return r;
}

// packed weight offsets
#define OW0 0
#define OB0 128
#define OW1 144
#define OB1 400
#define OW2 416
#define OB2 608
#define OW3 620
#define OB3 716
#define OW4 724
#define OB4 756
#define OW5 760
#define OB5 776
#define OW6 780
#define OB6 784

// ---------- kernel: pack MLP weights contiguously ----------
__global__ void __launch_bounds__(128) k_packw(
    const float* __restrict__ Wfm, const float* __restrict__ bfm,
    const float* __restrict__ Wc1, const float* __restrict__ bc1,
    const float* __restrict__ Wp1, const float* __restrict__ bp1,
    const float* __restrict__ Wc2, const float* __restrict__ bc2,
    const float* __restrict__ Wp2, const float* __restrict__ bp2,
    const float* __restrict__ Wc3, const float* __restrict__ bc3,
    const float* __restrict__ Wh,  const float* __restrict__ bh)
{
    int t = threadIdx.x;
    g_wt[OW0 + t] = Wfm[t];
    if (t < 16)  g_wt[OB0 + t] = bfm[t];
    g_wt[OW1 + t]       = Wc1[t];
    g_wt[OW1 + 128 + t] = Wc1[128 + t];
    if (t < 16)  g_wt[OB1 + t] = bc1[t];
    g_wt[OW2 + t] = Wp1[t];
    if (t < 64)  g_wt[OW2 + 128 + t] = Wp1[128 + t];
    if (t < 12)  g_wt[OB2 + t] = bp1[t];
    if (t < 96)  g_wt[OW3 + t] = Wc2[t];
    if (t < 8)   g_wt[OB3 + t] = bc2[t];
    if (t < 32)  g_wt[OW4 + t] = Wp2[t];
    if (t < 4)   g_wt[OB4 + t] = bp2[t];
    if (t < 16)  g_wt[OW5 + t] = Wc3[t];
    if (t < 4)   g_wt[OB5 + t] = bc3[t];
    if (t < 4)   g_wt[OW6 + t] = Wh[t];
    if (t == 0)  g_wt[OB6] = bh[0];
}

// ---------- kernel: normalize features ----------
__global__ void __launch_bounds__(128) k_prep(const float* __restrict__ x) {
    int i = blockIdx.x * 128 + threadIdx.x;
    float4 a = *(const float4*)(x + i * FF);
    float4 b = *(const float4*)(x + i * FF + 4);
    float s = a.x*a.x + a.y*a.y + a.z*a.z + a.w*a.w
            + b.x*b.x + b.y*b.y + b.z*b.z + b.w*b.w;
    float inv = 1.0f / (sqrtf(s) + 1e-12f);
    a.x *= inv; a.y *= inv; a.z *= inv; a.w *= inv;
    b.x *= inv; b.y *= inv; b.z *= inv; b.w *= inv;
    *(float4*)(g_xn + i * FF)     = a;
    *(float4*)(g_xn + i * FF + 4) = b;
}

// ---------- kernel: fidelity hits over upper-triangle 128x128 tiles ----------
__global__ void __launch_bounds__(FTPB) k_fid(const float* __restrict__ adj,
                                              const float* __restrict__ x) {
    __shared__ ull  sIp[TILE * FF];
    __shared__ float sJ[FF][TILE];

    int b = blockIdx.x;
    int ti = (int)(((2 * NT + 1) - sqrtf((float)((2 * NT + 1) * (2 * NT + 1)) - 8.0f * (float)b)) * 0.5f);
    if (ti < 0) ti = 0;
    if (ti > NT - 1) ti = NT - 1;
#define RS(r) ((r) * NT - ((r) * ((r) - 1)) / 2)
    while (ti > 0 && RS(ti) > b) --ti;
    while (RS(ti + 1) <= b) ++ti;
    int tj = ti + (b - RS(ti));
#undef RS

    int t = threadIdx.x;
    {
        int r = t & 127;
        int row = ((t < 128) ? ti : tj) * TILE + r;
        float4 a = *(const float4*)(g_xn + row * FF);
        float4 c = *(const float4*)(g_xn + row * FF + 4);
        float v[8] = {a.x, a.y, a.z, a.w, c.x, c.y, c.z, c.w};
        if (t < 128) {
#pragma unroll
            for (int f = 0; f < FF; ++f) sIp[r * FF + f] = pk2(v[f], v[f]);
        } else {
#pragma unroll
            for (int f = 0; f < FF; ++f) sJ[f][r] = v[f];
        }
    }
    __syncthreads();

    int w = t >> 5, lane = t & 31;
    int j0 = lane * 4;
    ull xj0[FF], xj1[FF];
#pragma unroll
    for (int f = 0; f < FF; ++f) {
        float4 v = *(const float4*)&sJ[f][j0];
        xj0[f] = pk2(v.x, v.y);
        xj1[f] = pk2(v.z, v.w);
    }
    int gjb = tj * TILE + j0;

#pragma unroll 8
    for (int ii = 0; ii < 16; ++ii) {
        int i = w * 16 + ii;
        ull d0 = 0ULL, d1 = 0ULL;
#pragma unroll
        for (int f = 0; f < FF; ++f) {
            ull xi = sIp[i * FF + f];
            fma2(d0, xi, xj0[f]);
            fma2(d1, xi, xj1[f]);
        }
        float da, db, dc, dd;
        up2(da, db, d0); up2(dc, dd, d1);
        int gi = ti * TILE + i;
        bool h0 = (da * da >= THRESH) && (gi < gjb + 0);
        bool h1 = (db * db >= THRESH) && (gi < gjb + 1);
        bool h2 = (dc * dc >= THRESH) && (gi < gjb + 2);
        bool h3 = (dd * dd >= THRESH) && (gi < gjb + 3);
        if (h0 | h1 | h2 | h3) {
            float4 xia = *(const float4*)(x + gi * FF);
            float4 xib = *(const float4*)(x + gi * FF + 4);
            float xi8[8] = {xia.x, xia.y, xia.z, xia.w, xib.x, xib.y, xib.z, xib.w};
            bool hh[4] = {h0, h1, h2, h3};
#pragma unroll
            for (int k = 0; k < 4; ++k) {
                if (hh[k]) {
                    int gj = gjb + k;
                    float aij = __ldg(adj + (size_t)gi * NN + gj);
                    float aji = __ldg(adj + (size_t)gj * NN + gi);
                    float wi = 1.0f - aij, wj = 1.0f - aji;
#pragma unroll
                    for (int f = 0; f < FF; ++f) {
                        atomicAdd(&g_corr[gi * FF + f], wi * __ldg(x + gj * FF + f));
                        atomicAdd(&g_corr[gj * FF + f], wj * xi8[f]);
                    }
                }
            }
        }
    }
}

// ---------- kernel: stream adjacency, double-buffered prefetch, CH=1024 ----
__global__ void __launch_bounds__(ATPB, 4) k_adj(const float* __restrict__ adj,
                                                 const float* __restrict__ x) {
    __shared__ float sx[FF][CH];   // 32 KB

    int tid = threadIdx.x, warp = tid >> 5, lane = tid & 31;
    int rowbase = blockIdx.x * 16 + warp * 4;
    const float* ap = adj + (size_t)rowbase * NN + lane * 4;

    ull acc[16];   // [r*4+p] : packed (f=2p, f=2p+1) sums
#pragma unroll
    for (int k = 0; k < 16; ++k) acc[k] = 0ULL;

    float4 Abuf[8], Bbuf[8];

#define LOADQ(BUF, OFF) do {                                                    \
    _Pragma("unroll")                                                           \
    for (int r = 0; r < 4; ++r) {                                               \
        BUF[r * 2 + 0] = __ldcs((const float4*)(ap + (size_t)r * NN + (OFF)));  \
        BUF[r * 2 + 1] = __ldcs((const float4*)(ap + (size_t)r * NN + (OFF) + 128)); \
    } } while (0)

#define GETC(V, J) ((J) == 0 ? (V).x : (J) == 1 ? (V).y : (J) == 2 ? (V).z : (V).w)

#define COMPUTE(BUF, BASE) do {                                                 \
    _Pragma("unroll")                                                           \
    for (int ph = 0; ph < 2; ++ph) {                                            \
        int jl = (BASE) + ph * 128 + lane * 4;                                  \
        float4 X0 = *(const float4*)&sx[0][jl];                                 \
        float4 X1 = *(const float4*)&sx[1][jl];                                 \
        float4 X2 = *(const float4*)&sx[2][jl];                                 \
        float4 X3 = *(const float4*)&sx[3][jl];                                 \
        float4 X4 = *(const float4*)&sx[4][jl];                                 \
        float4 X5 = *(const float4*)&sx[5][jl];                                 \
        float4 X6 = *(const float4*)&sx[6][jl];                                 \
        float4 X7 = *(const float4*)&sx[7][jl];                                 \
        _Pragma("unroll")                                                       \
        for (int jj = 0; jj < 4; ++jj) {                                        \
            ull p0 = pk2(GETC(X0, jj), GETC(X1, jj));                           \
            ull p1 = pk2(GETC(X2, jj), GETC(X3, jj));                           \
            ull p2 = pk2(GETC(X4, jj), GETC(X5, jj));                           \
            ull p3 = pk2(GETC(X6, jj), GETC(X7, jj));                           \
            _Pragma("unroll")                                                   \
            for (int r = 0; r < 4; ++r) {                                       \
                float a = GETC(BUF[r * 2 + ph], jj);                            \
                ull ad = pk2(a, a);                                             \
                fma2(acc[r * 4 + 0], ad, p0);                                   \
                fma2(acc[r * 4 + 1], ad, p1);                                   \
                fma2(acc[r * 4 + 2], ad, p2);                                   \
                fma2(acc[r * 4 + 3], ad, p3);                                   \
            } } } } while (0)

    LOADQ(Abuf, 0);   // prime: j = 0..255 (relative to chunk)

#pragma unroll 1
    for (int c = 0; c < NN; c += CH) {
        __syncthreads();
        const float4* xs = (const float4*)x + c * 2;
#pragma unroll
        for (int k = 0; k < 16; ++k) {
            int idx = tid + k * ATPB;
            float4 v = __ldg(xs + idx);
            int j = idx >> 1, fb = (idx & 1) << 2;
            sx[fb + 0][j] = v.x; sx[fb + 1][j] = v.y;
            sx[fb + 2][j] = v.z; sx[fb + 3][j] = v.w;
        }
        __syncthreads();

        LOADQ(Bbuf, c + 256);
        COMPUTE(Abuf, 0);
        LOADQ(Abuf, c + 512);
        COMPUTE(Bbuf, 256);
        LOADQ(Bbuf, c + 768);
        COMPUTE(Abuf, 512);
        if (c + CH < NN) LOADQ(Abuf, c + CH);
        COMPUTE(Bbuf, 768);
    }

    float v[32];
#pragma unroll
    for (int r = 0; r < 4; ++r)
#pragma unroll
        for (int p = 0; p < 4; ++p)
            up2(v[r * 8 + 2 * p], v[r * 8 + 2 * p + 1], acc[r * 4 + p]);
#pragma unroll
    for (int o = 16; o; o >>= 1)
#pragma unroll
        for (int k = 0; k < 32; ++k) v[k] += __shfl_xor_sync(0xffffffffu, v[k], o);

    g_sums[(rowbase + (lane >> 3)) * FF + (lane & 7)] = v[lane];
}

// ---------- kernel: per-row MLP tail ----------
__global__ void __launch_bounds__(128) k_post(float* __restrict__ out) {
    __shared__ float swt[792];
    int tid = threadIdx.x;
#pragma unroll
    for (int k = 0; k < 7; ++k) {
        int idx = tid + k * 128;
        if (idx < 792) swt[idx] = g_wt[idx];
    }
    __syncthreads();

    int row = blockIdx.x * 128 + tid;
    float s[8];
#pragma unroll
    for (int f = 0; f < FF; ++f) s[f] = g_sums[row * FF + f] + g_corr[row * FF + f];

    float h0[16];
#pragma unroll
    for (int o = 0; o < 16; ++o) {
        float t = swt[OB0 + o];
#pragma unroll
        for (int i = 0; i < 8; ++i) t = fmaf(s[i], swt[OW0 + i * 16 + o], t);
        h0[o] = tanh_a(t);
    }
    float h1[16];
#pragma unroll
    for (int o = 0; o < 16; ++o) {
        float t = swt[OB1 + o];
#pragma unroll
        for (int i = 0; i < 16; ++i) t = fmaf(h0[i], swt[OW1 + i * 16 + o], t);
        h1[o] = tanh_a(t);
    }
    float h2[12];
#pragma unroll
    for (int o = 0; o < 12; ++o) {
        float t = swt[OB2 + o];
#pragma unroll
        for (int i = 0; i < 16; ++i) t = fmaf(h1[i], swt[OW2 + i * 12 + o], t);
        h2[o] = tanh_a(t);
    }
    float h3[8];
#pragma unroll
    for (int o = 0; o < 8; ++o) {
        float t = swt[OB3 + o];
#pragma unroll
        for (int i = 0; i < 12; ++i) t = fmaf(h2[i], swt[OW3 + i * 8 + o], t);
        h3[o] = tanh_a(t);
    }
    float h4[4];
#pragma unroll
    for (int o = 0; o < 4; ++o) {
        float t = swt[OB4 + o];
#pragma unroll
        for (int i = 0; i < 8; ++i) t = fmaf(h3[i], swt[OW4 + i * 4 + o], t);
        h4[o] = tanh_a(t);
    }
    float h5[4];
#pragma unroll
    for (int o = 0; o < 4; ++o) {
        float t = swt[OB5 + o];
#pragma unroll
        for (int i = 0; i < 4; ++i) t = fmaf(h4[i], swt[OW5 + i * 4 + o], t);
        h5[o] = tanh_a(t);
    }
    float z = swt[OB6];
#pragma unroll
    for (int i = 0; i < 4; ++i) z = fmaf(h5[i], swt[OW6 + i], z);
    out[row] = 1.0f / (1.0f + expf(-z));
}

extern "C" void kernel_launch(void* const* d_in, const int* in_sizes, int n_in,
                              void* d_out, int out_size) {
    const float* adj = (const float*)d_in[0];
    const float* x   = (const float*)d_in[1];
    const float* Wfm = (const float*)d_in[2];
    const float* bfm = (const float*)d_in[3];
    const float* Wc1 = (const float*)d_in[4];
    const float* bc1 = (const float*)d_in[5];
    const float* Wp1 = (const float*)d_in[6];
    const float* bp1 = (const float*)d_in[7];
    const float* Wc2 = (const float*)d_in[8];
    const float* bc2 = (const float*)d_in[9];
    const float* Wp2 = (const float*)d_in[10];
    const float* bp2 = (const float*)d_in[11];
    const float* Wc3 = (const float*)d_in[12];
    const float* bc3 = (const float*)d_in[13];
    const float* Wh  = (const float*)d_in[14];
    const float* bh  = (const float*)d_in[15];
    float* out = (float*)d_out;

    static cudaStream_t s2 = nullptr;
    static cudaEvent_t e0 = nullptr, e1 = nullptr;
    if (s2 == nullptr) {
        cudaStreamCreateWithFlags(&s2, cudaStreamNonBlocking);
        cudaEventCreateWithFlags(&e0, cudaEventDisableTiming);
        cudaEventCreateWithFlags(&e1, cudaEventDisableTiming);
    }

    void* corr_ptr = nullptr;
    cudaGetSymbolAddress(&corr_ptr, g_corr);

    // k_adj issued first (fully resident); fid branch time-shares idle slots.
    cudaEventRecord(e0, 0);
    k_adj<<<NN / 16, ATPB>>>(adj, x);

    cudaStreamWaitEvent(s2, e0, 0);
    cudaMemsetAsync(corr_ptr, 0, NN * FF * sizeof(float), s2);
    k_packw<<<1, 128, 0, s2>>>(Wfm, bfm, Wc1, bc1, Wp1, bp1, Wc2, bc2,
                               Wp2, bp2, Wc3, bc3, Wh, bh);
    k_prep<<<NN / 128, 128, 0, s2>>>(x);
    k_fid<<<NFIDB, FTPB, 0, s2>>>(adj, x);
    cudaEventRecord(e1, s2);

    cudaStreamWaitEvent(0, e1, 0);
    k_post<<<NN / 128, 128>>>(out);
}